// round 6
// baseline (speedup 1.0000x reference)
#include <cuda_runtime.h>
#include <math.h>
#include <stdint.h>

#define B 16
#define T 2048
#define D 512
#define C 512
#define KW 11
#define KHALF 5
#define THRESH 0.9f
#define MAXTOK 128
#define TILE 32   // t-tile per k_logit block

// ---------------- scratch (no allocation allowed) ----------------
__device__ __align__(16) float g_weff[KW * D];
__device__ float g_beff;
__device__ float g_logit[B * T];
__device__ __align__(16) float g_anorm[B * T];  // alpha_norm
__device__ int   g_fire_t[B * MAXTOK];          // fire time of token n
__device__ float g_fak1[B * MAXTOK];            // ak1 at fire n
__device__ float g_fak2[B * MAXTOK];            // ak2 at fire n
__device__ int   g_nf[B];                       // number of fired tokens

// ---- packed f32x2 helpers (sm_103a) ----
__device__ __forceinline__ unsigned long long pack2(float a, float b) {
    unsigned long long r;
    asm("mov.b64 %0, {%1, %2};" : "=l"(r) : "f"(a), "f"(b));
    return r;
}
__device__ __forceinline__ void unpack2(unsigned long long v, float& a, float& b) {
    asm("mov.b64 {%0, %1}, %2;" : "=f"(a), "=f"(b) : "l"(v));
}
#define FMA2(accv, av, bv) \
    asm("fma.rn.f32x2 %0, %1, %2, %0;" : "+l"(accv) : "l"(av), "l"(bv))

// ---------------- kernel 1: fold projection into conv weights ----------------
__global__ void k_weff(const float* __restrict__ conv_w,
                       const float* __restrict__ conv_b,
                       const float* __restrict__ proj_w,
                       const float* __restrict__ proj_b) {
    int wid  = blockIdx.x * (blockDim.x >> 5) + (threadIdx.x >> 5);
    int lane = threadIdx.x & 31;
    if (wid < KW * D) {
        const float* row = conv_w + (size_t)wid * C;
        float s = 0.f;
        #pragma unroll 4
        for (int c = lane; c < C; c += 32) s += row[c] * proj_w[c];
        #pragma unroll
        for (int o = 16; o; o >>= 1) s += __shfl_down_sync(0xffffffffu, s, o);
        if (lane == 0) g_weff[wid] = s;
    } else if (wid == KW * D) {
        float s = 0.f;
        for (int c = lane; c < C; c += 32) s += conv_b[c] * proj_w[c];
        #pragma unroll
        for (int o = 16; o; o >>= 1) s += __shfl_down_sync(0xffffffffu, s, o);
        if (lane == 0) g_beff = s + proj_b[0];
    }
}

// ---------------- kernel 2: direct conv logits, register sliding window ------
__global__ void __launch_bounds__(128, 3)
k_logit(const float* __restrict__ eouts) {
    int b = blockIdx.y;
    int t0 = blockIdx.x * TILE;
    int tid = threadIdx.x;  // 0..127

    unsigned long long w01[KW], w23[KW];
    #pragma unroll
    for (int k = 0; k < KW; k++) {
        float4 w = ((const float4*)(g_weff + k * D))[tid];
        w01[k] = pack2(w.x, w.y);
        w23[k] = pack2(w.z, w.w);
    }

    unsigned long long acc[TILE];
    unsigned long long z = pack2(0.f, 0.f);
    #pragma unroll
    for (int i = 0; i < TILE; i++) acc[i] = z;

    const float4* eb = (const float4*)(eouts + (size_t)b * T * D);
    #pragma unroll
    for (int tt = 0; tt < TILE + 2 * KHALF; tt++) {
        int t = t0 + tt - KHALF;
        float4 v = make_float4(0.f, 0.f, 0.f, 0.f);
        if (t >= 0 && t < T) v = eb[(size_t)t * (D / 4) + tid];
        unsigned long long v01 = pack2(v.x, v.y);
        unsigned long long v23 = pack2(v.z, v.w);
        #pragma unroll
        for (int k = 0; k < KW; k++) {
            int i = tt - k;
            if (i >= 0 && i < TILE) {
                FMA2(acc[i], v01, w01[k]);
                FMA2(acc[i], v23, w23[k]);
            }
        }
    }

    __shared__ float s[TILE][129];
    #pragma unroll
    for (int i = 0; i < TILE; i++) {
        float lo, hi;
        unpack2(acc[i], lo, hi);
        s[i][tid] = lo + hi;
    }
    __syncthreads();
    __shared__ float s2[TILE][4];
    {
        int i = tid >> 2, seg = tid & 3;
        float sum = 0.f;
        #pragma unroll
        for (int j = 0; j < 32; j++) sum += s[i][seg * 32 + j];
        s2[i][seg] = sum;
    }
    __syncthreads();
    if (tid < TILE) {
        float tot = s2[tid][0] + s2[tid][1] + s2[tid][2] + s2[tid][3] + g_beff;
        g_logit[b * T + t0 + tid] = tot;
    }
}

// ---------------- kernel 3: alpha + prefix + ballot fire search --------------
__global__ void k_alpha_scan(float* __restrict__ out_alpha,
                             const int* __restrict__ elens,
                             const int* __restrict__ ylens) {
    int b = blockIdx.x;
    int tid = threadIdx.x;
    int lane = tid & 31, wid = tid >> 5;

    __shared__ float  sA[T];        // alpha_norm
    __shared__ double sS[T];        // inclusive prefix of alpha_norm
    __shared__ double sWarp[32];
    __shared__ int    s_fire_t[MAXTOK];
    __shared__ float  s_ak1[MAXTOK], s_ak2[MAXTOK];
    __shared__ float  s_asum;

    int el = elens[b];
    int yl = ylens[b];

    // --- step 1: sigmoid alphas + block reduce for asum ---
    float a0, a1;
    {
        double local = 0.0;
        #pragma unroll
        for (int rep = 0; rep < 2; rep++) {
            int t = tid + rep * 1024;
            float lg = g_logit[b * T + t];
            float a = 1.f / (1.f + expf(-lg));
            if (rep == 0) a0 = a; else a1 = a;
            local += (double)a;
        }
        #pragma unroll
        for (int o = 16; o; o >>= 1) local += __shfl_down_sync(0xffffffffu, local, o);
        if (lane == 0) sWarp[wid] = local;
        __syncthreads();
        if (wid == 0) {
            double v = sWarp[lane];
            #pragma unroll
            for (int o = 16; o; o >>= 1) v += __shfl_down_sync(0xffffffffu, v, o);
            if (lane == 0) s_asum = (float)v;
        }
        __syncthreads();
    }
    float asum = s_asum;
    float ylf = (float)yl;

    // --- step 2: alpha_norm ---
    {
        int t0 = tid, t1 = tid + 1024;
        float an0 = a0 / asum * ylf;
        float an1 = a1 / asum * ylf;
        sA[t0] = an0; sA[t1] = an1;
        out_alpha[b * T + t0] = a0;  out_alpha[b * T + t1] = a1;
        g_anorm[b * T + t0] = an0;   g_anorm[b * T + t1] = an1;
    }
    __syncthreads();

    // --- step 3: block inclusive prefix scan (double) ---
    {
        float e0 = sA[2 * tid], e1 = sA[2 * tid + 1];
        double my = (double)e0 + (double)e1;
        double v = my;
        #pragma unroll
        for (int o = 1; o < 32; o <<= 1) {
            double n = __shfl_up_sync(0xffffffffu, v, o);
            if (lane >= o) v += n;
        }
        if (lane == 31) sWarp[wid] = v;
        __syncthreads();
        if (wid == 0) {
            double w = sWarp[lane];
            #pragma unroll
            for (int o = 1; o < 32; o <<= 1) {
                double n = __shfl_up_sync(0xffffffffu, w, o);
                if (lane >= o) w += n;
            }
            sWarp[lane] = w;
        }
        __syncthreads();
        double base = (wid ? sWarp[wid - 1] : 0.0) + (v - my);
        sS[2 * tid]     = base + (double)e0;
        sS[2 * tid + 1] = base + (double)e0 + (double)e1;
    }
    __syncthreads();

    // --- step 4: warp 0 finds fires via monotone ballot sweep ---
    if (wid == 0) {
        double Ccorr = 0.0;
        int ntok = 0;
        int pos = 0;
        while (ntok < yl) {
            double th = (double)THRESH - Ccorr;
            int found = -1;
            for (int base = pos; base < el; base += 32) {
                int t = base + lane;
                bool hit = (t < el) && (sS[t] >= th);
                unsigned m = __ballot_sync(0xffffffffu, hit);
                if (m) { found = base + __ffs(m) - 1; break; }
            }
            if (found < 0) break;
            float a = sA[found];
            float acc = (float)(sS[found] + Ccorr);
            float ak1 = 1.f - acc;
            float ak2 = a - ak1;
            if (lane == 0) {
                s_fire_t[ntok] = found;
                s_ak1[ntok] = ak1;
                s_ak2[ntok] = ak2;
            }
            Ccorr += (double)a - 1.0;
            ntok++;
            pos = found + 1;
        }
        __syncwarp();
        if (lane == 0) g_nf[b] = ntok;
        for (int i = lane; i < ntok; i += 32) {
            g_fire_t[b * MAXTOK + i] = s_fire_t[i];
            g_fak1[b * MAXTOK + i] = s_ak1[i];
            g_fak2[b * MAXTOK + i] = s_ak2[i];
        }
    }
}

// ---------------- kernel 4: write aws rows fully (no memset) -----------------
// grid (L+1, B): block (b, r) writes row r of batch b completely.
// Row r: ak2_{r-1} at t=f_{r-1}; a_t for f_{r-1} < t < end; ak1_r at t=f_r;
//        zeros elsewhere. end = f_r (r<nf), el (r==nf<yl), else empty.
__global__ void __launch_bounds__(256)
k_aws(float* __restrict__ aws, const int* __restrict__ elens,
      const int* __restrict__ ylens, int L) {
    int b = blockIdx.y;
    int r = blockIdx.x;          // 0..L
    int tid = threadIdx.x;       // 0..255
    int nf = g_nf[b];
    float4* row = (float4*)(aws + ((size_t)b * (L + 1) + r) * T);

    if (r > nf) {
        float4 z = make_float4(0.f, 0.f, 0.f, 0.f);
        #pragma unroll
        for (int i = tid; i < T / 4; i += 256) row[i] = z;
        return;
    }
    int el = elens[b];
    int yl = ylens[b];
    int   fprev = (r > 0) ? g_fire_t[b * MAXTOK + r - 1] : -1;
    float vprev = (r > 0) ? g_fak2[b * MAXTOK + r - 1] : 0.f;
    int   fr   = (r < nf) ? g_fire_t[b * MAXTOK + r] : -2;
    float vak1 = (r < nf) ? g_fak1[b * MAXTOK + r] : 0.f;
    int aEnd = (r < nf) ? fr : ((r < yl) ? el : fprev);  // a_t for fprev<t<aEnd

    const float4* an4 = (const float4*)(g_anorm + b * T);
    #pragma unroll
    for (int i = tid; i < T / 4; i += 256) {
        float4 a4 = an4[i];
        float av[4] = {a4.x, a4.y, a4.z, a4.w};
        float ov[4];
        int t0 = 4 * i;
        #pragma unroll
        for (int j = 0; j < 4; j++) {
            int t = t0 + j;
            float v = 0.f;
            if (t > fprev && t < aEnd) v = av[j];
            else if (t == fprev)       v = vprev;   // fprev==-1 unreachable
            else if (t == fr)          v = vak1;
            ov[j] = v;
        }
        row[i] = make_float4(ov[0], ov[1], ov[2], ov[3]);
    }
}

// ---------------- kernel 5: per-token 8-phase reduction -> fired -------------
// block (1024 threads) per (token, batch); zero-fills rows n >= nf.
__global__ void __launch_bounds__(1024)
k_fired(const float* __restrict__ eouts, float* __restrict__ fired, int L) {
    int b = blockIdx.y;
    int n = blockIdx.x;
    int d  = threadIdx.x & 127;   // float4 slice of D
    int ph = threadIdx.x >> 7;    // 0..7 time phase
    int nf = g_nf[b];

    if (n >= nf) {                // zero-fill unused rows (replaces memset)
        if (ph == 0)
            ((float4*)(fired + ((size_t)b * L + n) * D))[d] =
                make_float4(0.f, 0.f, 0.f, 0.f);
        return;
    }

    int e = g_fire_t[b * MAXTOK + n];
    float c1 = g_fak1[b * MAXTOK + n];
    int s; float c0;
    if (n == 0) { s = -1; c0 = 0.f; }
    else { s = g_fire_t[b * MAXTOK + n - 1]; c0 = g_fak2[b * MAXTOK + n - 1]; }

    const float* an = g_anorm + b * T;
    const float4* eb = (const float4*)(eouts + (size_t)b * T * D);

    int t0 = (s >= 0) ? s : 0;
    float4 acc = make_float4(0.f, 0.f, 0.f, 0.f);
    #pragma unroll 2
    for (int t = t0 + ph; t <= e; t += 8) {
        float w = (t == e) ? c1 : ((t == s) ? c0 : an[t]);
        float4 v = eb[(size_t)t * 128 + d];
        acc.x += w * v.x; acc.y += w * v.y;
        acc.z += w * v.z; acc.w += w * v.w;
    }

    __shared__ float4 sAcc[1024];
    sAcc[threadIdx.x] = acc;
    __syncthreads();
    if (ph == 0) {
        #pragma unroll
        for (int p = 1; p < 8; p++) {
            float4 a = sAcc[p * 128 + d];
            acc.x += a.x; acc.y += a.y; acc.z += a.z; acc.w += a.w;
        }
        ((float4*)(fired + ((size_t)b * L + n) * D))[d] = acc;
    }
}

// ---------------- launch ------------------------------------------------------
extern "C" void kernel_launch(void* const* d_in, const int* in_sizes, int n_in,
                              void* d_out, int out_size) {
    const float* eouts  = (const float*)d_in[0];
    const float* conv_w = (const float*)d_in[1];
    const float* conv_b = (const float*)d_in[2];
    const float* proj_w = (const float*)d_in[3];
    const float* proj_b = (const float*)d_in[4];
    const int*   elens  = (const int*)d_in[5];
    const int*   ylens  = (const int*)d_in[6];

    // out = concat(fired[B,L,D], alpha[B,T], aws[B,1,L+1,T])
    int L = (out_size - 2 * B * T) / (B * D + B * T);

    float* out   = (float*)d_out;
    float* fired = out;
    float* alpha = out + (size_t)B * L * D;
    float* aws   = alpha + (size_t)B * T;

    k_weff<<<(KW * D + 1 + 7) / 8, 256>>>(conv_w, conv_b, proj_w, proj_b);
    k_logit<<<dim3(T / TILE, B), 128>>>(eouts);
    k_alpha_scan<<<B, 1024>>>(alpha, elens, ylens);
    k_aws<<<dim3(L + 1, B), 256>>>(aws, elens, ylens, L);
    k_fired<<<dim3(L, B), 1024>>>(eouts, fired, L);
}